// round 11
// baseline (speedup 1.0000x reference)
#include <cuda_runtime.h>

#define PP 8
#define TT 128
#define BPB 2
#define NT 64
#define MAXB 8192

typedef unsigned long long ull;

struct Params {
  const float* feat; const float* hist; const int* relation; const int* pfl;
  const float* emb_phase; const float* w_veh; const float* b_veh;
  const float* w_hist; const float* b_hist;
  const float* gwih; const float* gwhh; const float* gbih; const float* gbhh;
  const float* w_lane; const float* b_lane; const float* emb_const;
  const float* wf; const float* bf; const float* wc; const float* bc;
  const float* wz; const float* bz; const float* wo; const float* bo;
  float* out; int B;
};

// scratch (static device memory — no allocations)
__device__ __align__(16) float4 g_xbuf[(size_t)MAXB * TT * PP];

__device__ __forceinline__ ull pk2(float v) {
  ull d; asm("mov.b64 %0, {%1, %1};" : "=l"(d) : "f"(v)); return d;
}
__device__ __forceinline__ ull pk2b(float lo, float hi) {
  ull d; asm("mov.b64 %0, {%1, %2};" : "=l"(d) : "f"(lo), "f"(hi)); return d;
}
__device__ __forceinline__ ull f2fma(ull a, ull b, ull c) {
  ull d; asm("fma.rn.f32x2 %0, %1, %2, %3;" : "=l"(d) : "l"(a), "l"(b), "l"(c)); return d;
}
__device__ __forceinline__ ull add2(ull a, ull b) {
  ull d; asm("add.rn.f32x2 %0, %1, %2;" : "=l"(d) : "l"(a), "l"(b)); return d;
}
__device__ __forceinline__ void upk(ull v, float& lo, float& hi) {
  asm("mov.b64 {%0, %1}, %2;" : "=f"(lo), "=f"(hi) : "l"(v));
}
__device__ __forceinline__ float loF(ull v) { float a, b; upk(v, a, b); return a; }
__device__ __forceinline__ float hiF(ull v) { float a, b; upk(v, a, b); return b; }
__device__ __forceinline__ float tanh_ap(float x) {
  float y; asm("tanh.approx.f32 %0, %1;" : "=f"(y) : "f"(x)); return y;
}
__device__ __forceinline__ float sigf(float v) {
  return fmaf(tanh_ap(0.5f * v), 0.5f, 0.5f);
}

// ---------------- precompute x = sigmoid(hist @ w_hist + b_hist) ----------------
__global__ __launch_bounds__(256) void precomp_x(const float* __restrict__ hist,
                                                 const float* __restrict__ w_hist,
                                                 const float* __restrict__ b_hist, int B) {
  long idx = (long)blockIdx.x * blockDim.x + threadIdx.x;   // over B*T
  if (idx >= (long)B * TT) return;
  const float4* row4 = reinterpret_cast<const float4*>(hist + idx * 24);
  float q[24];
  float4 rr;
#pragma unroll
  for (int i = 0; i < 6; i++) {
    rr = row4[i];
    q[4 * i] = rr.x; q[4 * i + 1] = rr.y; q[4 * i + 2] = rr.z; q[4 * i + 3] = rr.w;
  }
  float w[12], bb[4];
#pragma unroll
  for (int i = 0; i < 12; i++) w[i] = w_hist[i];
#pragma unroll
  for (int j = 0; j < 4; j++) bb[j] = b_hist[j];
  float4* dst = &g_xbuf[idx * PP];
#pragma unroll
  for (int p = 0; p < PP; p++) {
    float q0 = q[p], q1 = q[8 + p], q2 = q[16 + p];
    float4 x;
    x.x = sigf(fmaf(q0, w[0], fmaf(q1, w[4], fmaf(q2, w[8],  bb[0]))));
    x.y = sigf(fmaf(q0, w[1], fmaf(q1, w[5], fmaf(q2, w[9],  bb[1]))));
    x.z = sigf(fmaf(q0, w[2], fmaf(q1, w[6], fmaf(q2, w[10], bb[2]))));
    x.w = sigf(fmaf(q0, w[3], fmaf(q1, w[7], fmaf(q2, w[11], bb[3]))));
    dst[p] = x;
  }
}

// ---------------- main GRU + tail kernel ----------------
// 4 threads per (batch,lane): s = hidden half, c = reduction split.
// Weights: kk 0..3 in registers (64 regs); kk 4..6 + biases in a bank-padded
// smem table reloaded each step (18 LDS.128, conflict-free broadcast).
// Target: <=128 regs -> 8 CTAs/SM (16 warps) vs Round-7's 6 CTAs.
__global__ __launch_bounds__(NT, 8) void gru_kernel(Params pr) {
  __shared__ float embph_s[8], wveh_s[4], bveh_s[4];
  __shared__ float wlane_s[18 * 16], blane_s[16];
  __shared__ float wf_s[32 * 20], bf_s[20];
  __shared__ float wz_s[20 * 20], bz_s[20];
  __shared__ float wo_s[20];
  __shared__ float bo_s;
  __shared__ float wc_s[4 * 20], bc_s[20], embc_s[8];
  __shared__ int rel_s[56], pfl_s[PP];
  __shared__ float press_s[BPB * PP * 17];
  __shared__ float v_s[BPB * PP * 21];
  // GRU weight/bias table: combo (2s+c) stride 84 floats (336B, 16B-aligned;
  // combo bank offsets {0,20,8,28} -> the 4 concurrent 16B broadcasts are
  // conflict-free). Layout per combo: kk4 row [0:16), kk5 [16:32), kk6 [32:48),
  // bias pairs [48:70).
  __shared__ __align__(16) float wq_s[4 * 84];

  const int tid = threadIdx.x;
  const int bl   = tid >> 5;
  const int p    = (tid >> 2) & 7;
  const int s    = (tid >> 1) & 1;
  const int cbit = tid & 1;
  const bool c0  = (cbit == 0);
  const int tq   = tid & 3;

  // stage 0: tail weights -> smem
  if (tid < 8) embph_s[tid] = pr.emb_phase[tid];
  if (tid < 4) { wveh_s[tid] = pr.w_veh[tid]; bveh_s[tid] = pr.b_veh[tid]; }
  for (int i = tid; i < 288; i += NT) wlane_s[i] = pr.w_lane[i];
  if (tid < 16) blane_s[tid] = pr.b_lane[tid];
  for (int i = tid; i < 640; i += NT) wf_s[i] = pr.wf[i];
  if (tid < 20) bf_s[tid] = pr.bf[tid];
  for (int i = tid; i < 400; i += NT) wz_s[i] = pr.wz[i];
  if (tid < 20) bz_s[tid] = pr.bz[tid];
  if (tid < 20) wo_s[tid] = pr.wo[tid];
  if (tid == 0) bo_s = pr.bo[0];
  for (int i = tid; i < 80; i += NT) wc_s[i] = pr.wc[i];
  if (tid < 20) bc_s[tid] = pr.bc[tid];
  if (tid < 8) embc_s[tid] = pr.emb_const[tid];
  if (tid < 56) rel_s[tid] = pr.relation[tid];
  if (tid < PP) pfl_s[tid] = pr.pfl[tid];

  const long b = (long)blockIdx.x * BPB + bl;
  const bool active = (b < (long)pr.B);
  const long bcl = active ? b : (long)(pr.B - 1);

  // ---- weight gather ----
  const float* gwih = pr.gwih;
  const float* gwhh = pr.gwhh;
  auto wat = [&](int kk, int pos) -> float {
    if (pos >= 15) return 0.f;
    int grow;
    if (pos < 10) { int j = pos >> 1, g = pos & 1; grow = g * 10 + 5 * s + j; }
    else          { grow = 20 + 5 * s + (pos - 10); }
    if (c0) {
      if (kk < 4) return gwih[grow * 4 + kk];
      return gwhh[grow * 10 + 5 * s + (kk - 4)];
    } else {
      int hcol = (kk < 2) ? (5 * s + 3 + kk) : (5 * (1 - s) + (kk - 2));
      return gwhh[grow * 10 + hcol];
    }
  };
  // kk 0..3 stay in registers (64 regs)
  ull w[4][8];
#pragma unroll
  for (int kk = 0; kk < 4; kk++)
#pragma unroll
    for (int i = 0; i < 8; i++)
      w[kk][i] = pk2b(wat(kk, 2 * i), wat(kk, 2 * i + 1));

  auto bat = [&](int pos) -> float {
    if (!c0) return 0.f;
    if (pos < 10) { int j = pos >> 1, g = pos & 1; int grow = g * 10 + 5 * s + j;
                    return pr.gbih[grow] + pr.gbhh[grow]; }
    if (pos >= 10 && pos < 15) return pr.gbih[20 + 5 * s + (pos - 10)];  // P (bih_n)
    if (pos >= 16 && pos < 21) return pr.gbhh[20 + 5 * s + (pos - 16)];  // Q (bhh_n)
    return 0.f;
  };
  // kk 4..6 + biases -> smem table (one writer thread per combo; duplicate
  // writers across warps write identical values — benign)
  if (p == 0) {
    const int combo = 2 * s + cbit;
    float* dst = &wq_s[combo * 84];
    for (int kq = 0; kq < 3; kq++)
      for (int pos = 0; pos < 16; pos++)
        dst[kq * 16 + pos] = wat(4 + kq, pos);
    for (int i = 0; i < 11; i++) {
      dst[48 + 2 * i]     = bat(2 * i);
      dst[48 + 2 * i + 1] = bat(2 * i + 1);
    }
    dst[70] = 0.f; dst[71] = 0.f;   // pad (last LDS.128 overreads)
  }
  __syncthreads();

  const ulonglong2* wq2 = reinterpret_cast<const ulonglong2*>(&wq_s[(2 * s + cbit) * 84]);

  // owned h (c0: h0,h1,h2 ; c1: h3,h4,[garbage]) and c1's other-half cache
  float hO[3] = {0.f, 0.f, 0.f};
  float hx0 = 0.f, hx1 = 0.f, hx2 = 0.f, hx3 = 0.f, hx4 = 0.f;

  const float4* xp = &g_xbuf[bcl * TT * PP + p];
  float4 xq = make_float4(0.f, 0.f, 0.f, 0.f);
  if (c0) xq = xp[0];                 // c1 never consumes x — skip its loads

  for (int t = 0; t < TT; t++) {
    float4 xn = make_float4(0.f, 0.f, 0.f, 0.f);
    if (t + 1 < TT && c0) xn = xp[(t + 1) * PP];

    float vals[7];
    vals[0] = c0 ? xq.x : hO[0];
    vals[1] = c0 ? xq.y : hO[1];
    vals[2] = c0 ? xq.z : hx0;
    vals[3] = c0 ? xq.w : hx1;
    vals[4] = c0 ? hO[0] : hx2;
    vals[5] = c0 ? hO[1] : hx3;
    vals[6] = c0 ? hO[2] : hx4;

    // ---- A init from smem bias pairs (loop-invariant addresses) ----
    ull A[11];
    {
      ulonglong2 b0 = wq2[12], b1 = wq2[13], b2 = wq2[14];
      ulonglong2 b3 = wq2[15], b4 = wq2[16], b5 = wq2[17];
      A[0] = b0.x; A[1] = b0.y; A[2] = b1.x; A[3] = b1.y;
      A[4] = b2.x; A[5] = b2.y; A[6] = b3.x; A[7] = b3.y;
      A[8] = b4.x; A[9] = b4.y; A[10] = b5.x;
    }
    // kk 0..3 from registers
#pragma unroll
    for (int kk = 0; kk < 4; kk++) {
      ull s2 = pk2(vals[kk]);
#pragma unroll
      for (int i = 0; i < 5; i++) A[i] = f2fma(s2, w[kk][i], A[i]);
      const int nb = 5;   // P bucket
#pragma unroll
      for (int i = 0; i < 3; i++) A[nb + i] = f2fma(s2, w[kk][5 + i], A[nb + i]);
    }
    // kk 4..6 from smem (Q bucket)
#pragma unroll
    for (int kq = 0; kq < 3; kq++) {
      ulonglong2 q0 = wq2[kq * 4 + 0], q1 = wq2[kq * 4 + 1];
      ulonglong2 q2 = wq2[kq * 4 + 2], q3 = wq2[kq * 4 + 3];
      ull s2 = pk2(vals[4 + kq]);
      A[0] = f2fma(s2, q0.x, A[0]);
      A[1] = f2fma(s2, q0.y, A[1]);
      A[2] = f2fma(s2, q1.x, A[2]);
      A[3] = f2fma(s2, q1.y, A[3]);
      A[4] = f2fma(s2, q2.x, A[4]);
      A[8]  = f2fma(s2, q2.y, A[8]);
      A[9]  = f2fma(s2, q3.x, A[9]);
      A[10] = f2fma(s2, q3.y, A[10]);
    }

    // c1 pre-sums its full h-side n partial (c0's S unused)
    ull S0 = add2(A[5], A[8]);
    ull S1 = add2(A[6], A[9]);
    ull S2 = add2(A[7], A[10]);

    // asymmetric exchange: 6 ull shfls
    ull r1 = __shfl_xor_sync(0xffffffffu, c0 ? A[3]  : A[0], 1);
    ull r2 = __shfl_xor_sync(0xffffffffu, c0 ? A[4]  : A[1], 1);
    ull r3 = __shfl_xor_sync(0xffffffffu, c0 ? A[6]  : A[2], 1);
    ull r4 = __shfl_xor_sync(0xffffffffu, c0 ? A[7]  : S0,   1);
    ull r5 = __shfl_xor_sync(0xffffffffu, c0 ? A[9]  : S1,   1);
    ull r6 = __shfl_xor_sync(0xffffffffu, c0 ? A[10] : S2,   1);

    // combined RZ for owned slots
    ull rz0 = add2(c0 ? A[0] : A[3], r1);     // c0: j0 ; c1: j3
    ull rz1 = add2(c0 ? A[1] : A[4], r2);     // c0: j1 ; c1: j4
    ull rz2 = add2(A[2], r3);                 // c0: j2 ; c1: garbage
    // c0 hn pairs
    ull hnp0 = add2(r4, A[8]);                // c0: {hn0,hn1}
    ull hnp1 = add2(r5, A[9]);                // c0: {hn2,hn3}

    float gA = c0 ? loF(A[5]) : hiF(r3);
    float hA = c0 ? loF(hnp0) : (hiF(S1) + hiF(r5));
    float gB = c0 ? hiF(A[5]) : loF(r4);
    float hB = c0 ? hiF(hnp0) : (loF(S2) + loF(r6));
    float gC = loF(A[6]);
    float hC = loF(hnp1);

    {
      float rl, zl;
      upk(rz0, rl, zl);
      float rr0 = sigf(rl), zz0 = sigf(zl);
      float nn0 = tanh_ap(fmaf(rr0, hA, gA));
      upk(rz1, rl, zl);
      float rr1 = sigf(rl), zz1 = sigf(zl);
      float nn1 = tanh_ap(fmaf(rr1, hB, gB));
      upk(rz2, rl, zl);
      float rr2 = sigf(rl), zz2 = sigf(zl);
      float nn2 = tanh_ap(fmaf(rr2, hC, gC));
      hO[0] = fmaf(zz0, hO[0] - nn0, nn0);
      hO[1] = fmaf(zz1, hO[1] - nn1, nn1);
      hO[2] = fmaf(zz2, hO[2] - nn2, nn2);   // c1: garbage, never consumed
    }

    // redistribute for next step: only c1 consumes these
    float w3a = __shfl_xor_sync(0xffffffffu, hO[0], 3);
    float w3b = __shfl_xor_sync(0xffffffffu, hO[1], 3);
    float w3c = __shfl_xor_sync(0xffffffffu, hO[2], 3);
    float w2a = __shfl_xor_sync(0xffffffffu, hO[0], 2);
    float w2b = __shfl_xor_sync(0xffffffffu, hO[1], 2);
    hx0 = w3a; hx1 = w3b; hx2 = w3c; hx3 = w2a; hx4 = w2b;

    xq = xn;
  }

  // ---- reassemble full h for tail ----
  float ha[10];
  {
    float t1 = __shfl_xor_sync(0xffffffffu, hO[0], 1);  // c0<-h3 ; c1<-h0
    float t2 = __shfl_xor_sync(0xffffffffu, hO[1], 1);  // c0<-h4 ; c1<-h1
    float t3 = __shfl_xor_sync(0xffffffffu, hO[2], 1);  //          c1<-h2
    float hf0 = c0 ? hO[0] : t1;
    float hf1 = c0 ? hO[1] : t2;
    float hf2 = c0 ? hO[2] : t3;
    float hf3 = c0 ? t1 : hO[0];
    float hf4 = c0 ? t2 : hO[1];
    float hg0 = __shfl_xor_sync(0xffffffffu, hf0, 2);
    float hg1 = __shfl_xor_sync(0xffffffffu, hf1, 2);
    float hg2 = __shfl_xor_sync(0xffffffffu, hf2, 2);
    float hg3 = __shfl_xor_sync(0xffffffffu, hf3, 2);
    float hg4 = __shfl_xor_sync(0xffffffffu, hf4, 2);
    float hf[5] = {hf0, hf1, hf2, hf3, hf4};
    float hg[5] = {hg0, hg1, hg2, hg3, hg4};
#pragma unroll
    for (int j = 0; j < 5; j++) {
      ha[j]     = (s == 0) ? hf[j] : hg[j];
      ha[5 + j] = (s == 0) ? hg[j] : hf[j];
    }
  }

  // ---- tail: lane projection -> pressure -> pair network ----
  {
    float lf[18];
    float veh = pr.feat[bcl * 16 + 8 + p];
    int pidx = (int)pr.feat[bcl * 16 + p];
#pragma unroll
    for (int j = 0; j < 4; j++) lf[j] = sigf(fmaf(veh, wveh_s[j], bveh_s[j]));
#pragma unroll
    for (int j = 0; j < 4; j++) lf[4 + j] = sigf(embph_s[pidx * 4 + j]);
#pragma unroll
    for (int i = 0; i < 10; i++) lf[8 + i] = ha[i];

    const int lrow = bl * 8 + p;
#pragma unroll
    for (int mm = 0; mm < 4; mm++) {
      int m = 4 * tq + mm;
      float acc = blane_s[m];
#pragma unroll
      for (int k = 0; k < 18; k++) acc = fmaf(lf[k], wlane_s[k * 16 + m], acc);
      press_s[lrow * 17 + m] = 2.0f * fmaxf(acc, 0.f);
    }
    __syncwarp();
    float pf[16];
#pragma unroll
    for (int k = 0; k < 16; k++) pf[k] = press_s[lrow * 17 + k];
#pragma unroll
    for (int mm = 0; mm < 5; mm++) {
      int m = 5 * tq + mm;
      float acc = 0.f;
#pragma unroll
      for (int k = 0; k < 16; k++) acc = fmaf(pf[k], wf_s[(16 + k) * 20 + m], acc);
      v_s[lrow * 21 + m] = acc;
    }
    __syncwarp();
  }
  {
    const int iph = p;
    const int li = pfl_s[iph];
    const float* pi = &press_s[(bl * 8 + li) * 17];

    float u[20];
#pragma unroll
    for (int m = 0; m < 20; m++) u[m] = bf_s[m];
#pragma unroll
    for (int k = 0; k < 16; k++) {
      float sv = pi[k];
#pragma unroll
      for (int m = 0; m < 20; m++) u[m] = fmaf(sv, wf_s[k * 20 + m], u[m]);
    }

    float acc = 0.f;
    const int jpS = tq * 2;
    const int jpN = (tq == 3) ? 1 : 2;
    for (int q = 0; q < jpN; q++) {
      int jp = jpS + q;
      int j = jp + (jp >= iph ? 1 : 0);
      int lj = pfl_s[j];
      const float* vj = &v_s[(bl * 8 + lj) * 21];
      int rel = rel_s[iph * 7 + jp];
      const float* e = &embc_s[rel * 4];
      float ttv[20];
#pragma unroll
      for (int m = 0; m < 20; m++) {
        float y = bc_s[m];
#pragma unroll
        for (int c = 0; c < 4; c++) y = fmaf(e[c], wc_s[c * 20 + m], y);
        y = fmaxf(y, 0.f);
        ttv[m] = fmaxf(u[m] + vj[m], 0.f) * y;
      }
      float z2[20];
#pragma unroll
      for (int m = 0; m < 20; m++) z2[m] = bz_s[m];
#pragma unroll
      for (int m = 0; m < 20; m++) {
        float sv = ttv[m];
#pragma unroll
        for (int m2 = 0; m2 < 20; m2++) z2[m2] = fmaf(sv, wz_s[m * 20 + m2], z2[m2]);
      }
      float zs = bo_s;
#pragma unroll
      for (int m2 = 0; m2 < 20; m2++) zs = fmaf(fmaxf(z2[m2], 0.f), wo_s[m2], zs);
      acc += zs;
    }
    acc += __shfl_xor_sync(0xffffffffu, acc, 1);
    acc += __shfl_xor_sync(0xffffffffu, acc, 2);
    if (tq == 0 && active) pr.out[b * PP + iph] = acc;
  }
}

extern "C" void kernel_launch(void* const* d_in, const int* in_sizes, int n_in,
                              void* d_out, int out_size) {
  Params pr;
  pr.feat      = (const float*)d_in[0];
  pr.hist      = (const float*)d_in[1];
  pr.relation  = (const int*)  d_in[2];
  pr.pfl       = (const int*)  d_in[3];
  pr.emb_phase = (const float*)d_in[4];
  pr.w_veh     = (const float*)d_in[5];
  pr.b_veh     = (const float*)d_in[6];
  pr.w_hist    = (const float*)d_in[7];
  pr.b_hist    = (const float*)d_in[8];
  pr.gwih      = (const float*)d_in[9];
  pr.gwhh      = (const float*)d_in[10];
  pr.gbih      = (const float*)d_in[11];
  pr.gbhh      = (const float*)d_in[12];
  pr.w_lane    = (const float*)d_in[13];
  pr.b_lane    = (const float*)d_in[14];
  pr.emb_const = (const float*)d_in[15];
  pr.wf        = (const float*)d_in[16];
  pr.bf        = (const float*)d_in[17];
  pr.wc        = (const float*)d_in[18];
  pr.bc        = (const float*)d_in[19];
  pr.wz        = (const float*)d_in[20];
  pr.bz        = (const float*)d_in[21];
  pr.wo        = (const float*)d_in[22];
  pr.bo        = (const float*)d_in[23];
  pr.out       = (float*)d_out;
  pr.B         = in_sizes[0] / (2 * PP);

  long bt = (long)pr.B * TT;
  precomp_x<<<(int)((bt + 255) / 256), 256>>>(pr.hist, pr.w_hist, pr.b_hist, pr.B);
  int grid = (pr.B + BPB - 1) / BPB;
  gru_kernel<<<grid, NT>>>(pr);
}

// round 12
// speedup vs baseline: 1.0322x; 1.0322x over previous
#include <cuda_runtime.h>

#define PP 8
#define TT 128
#define BPB 2
#define NT 64
#define MAXB 8192

typedef unsigned long long ull;

struct Params {
  const float* feat; const float* hist; const int* relation; const int* pfl;
  const float* emb_phase; const float* w_veh; const float* b_veh;
  const float* w_hist; const float* b_hist;
  const float* gwih; const float* gwhh; const float* gbih; const float* gbhh;
  const float* w_lane; const float* b_lane; const float* emb_const;
  const float* wf; const float* bf; const float* wc; const float* bc;
  const float* wz; const float* bz; const float* wo; const float* bo;
  float* out; int B;
};

// scratch (static device memory — no allocations)
__device__ __align__(16) float4 g_xbuf[(size_t)MAXB * TT * PP];

__device__ __forceinline__ ull pk2(float v) {
  ull d; asm("mov.b64 %0, {%1, %1};" : "=l"(d) : "f"(v)); return d;
}
__device__ __forceinline__ ull pk2b(float lo, float hi) {
  ull d; asm("mov.b64 %0, {%1, %2};" : "=l"(d) : "f"(lo), "f"(hi)); return d;
}
__device__ __forceinline__ ull f2fma(ull a, ull b, ull c) {
  ull d; asm("fma.rn.f32x2 %0, %1, %2, %3;" : "=l"(d) : "l"(a), "l"(b), "l"(c)); return d;
}
__device__ __forceinline__ ull add2(ull a, ull b) {
  ull d; asm("add.rn.f32x2 %0, %1, %2;" : "=l"(d) : "l"(a), "l"(b)); return d;
}
__device__ __forceinline__ void upk(ull v, float& lo, float& hi) {
  asm("mov.b64 {%0, %1}, %2;" : "=f"(lo), "=f"(hi) : "l"(v));
}
__device__ __forceinline__ float loF(ull v) { float a, b; upk(v, a, b); return a; }
__device__ __forceinline__ float hiF(ull v) { float a, b; upk(v, a, b); return b; }
__device__ __forceinline__ float tanh_ap(float x) {
  float y; asm("tanh.approx.f32 %0, %1;" : "=f"(y) : "f"(x)); return y;
}
__device__ __forceinline__ float sigf(float v) {
  return fmaf(tanh_ap(0.5f * v), 0.5f, 0.5f);
}

// ---------------- precompute x = sigmoid(hist @ w_hist + b_hist) ----------------
__global__ __launch_bounds__(256) void precomp_x(const float* __restrict__ hist,
                                                 const float* __restrict__ w_hist,
                                                 const float* __restrict__ b_hist, int B) {
  long idx = (long)blockIdx.x * blockDim.x + threadIdx.x;   // over B*T
  if (idx >= (long)B * TT) return;
  const float4* row4 = reinterpret_cast<const float4*>(hist + idx * 24);
  float q[24];
  float4 rr;
#pragma unroll
  for (int i = 0; i < 6; i++) {
    rr = row4[i];
    q[4 * i] = rr.x; q[4 * i + 1] = rr.y; q[4 * i + 2] = rr.z; q[4 * i + 3] = rr.w;
  }
  float w[12], bb[4];
#pragma unroll
  for (int i = 0; i < 12; i++) w[i] = w_hist[i];
#pragma unroll
  for (int j = 0; j < 4; j++) bb[j] = b_hist[j];
  float4* dst = &g_xbuf[idx * PP];
#pragma unroll
  for (int p = 0; p < PP; p++) {
    float q0 = q[p], q1 = q[8 + p], q2 = q[16 + p];
    float4 x;
    x.x = sigf(fmaf(q0, w[0], fmaf(q1, w[4], fmaf(q2, w[8],  bb[0]))));
    x.y = sigf(fmaf(q0, w[1], fmaf(q1, w[5], fmaf(q2, w[9],  bb[1]))));
    x.z = sigf(fmaf(q0, w[2], fmaf(q1, w[6], fmaf(q2, w[10], bb[2]))));
    x.w = sigf(fmaf(q0, w[3], fmaf(q1, w[7], fmaf(q2, w[11], bb[3]))));
    dst[p] = x;
  }
}

// ---------------- main GRU + tail kernel ----------------
// 4 threads per (batch,lane): s = hidden half, c = reduction split.
// Weights (112 regs) stay register-resident; biases live in a tiny bank-
// disjoint smem table reloaded each step (6 broadcast LDS.128, loop-invariant
// addresses). xq/hx unioned into u[5] (c0 holds x, c1 holds redistributed h).
// Target <=146 regs -> 7 CTAs/SM (14 warps).
__global__ __launch_bounds__(NT, 7) void gru_kernel(Params pr) {
  __shared__ float embph_s[8], wveh_s[4], bveh_s[4];
  __shared__ float wlane_s[18 * 16], blane_s[16];
  __shared__ float wf_s[32 * 20], bf_s[20];
  __shared__ float wz_s[20 * 20], bz_s[20];
  __shared__ float wo_s[20];
  __shared__ float bo_s;
  __shared__ float wc_s[4 * 20], bc_s[20], embc_s[8];
  __shared__ int rel_s[56], pfl_s[PP];
  __shared__ float press_s[BPB * PP * 17];
  __shared__ float v_s[BPB * PP * 21];
  // bias table: combo (tq) stride 24 floats (96B); simultaneous 16B reads of
  // the 4 combos hit banks {0-3},{24-27},{16-19},{8-11} -> conflict-free.
  __shared__ __align__(16) float bq_s[4 * 24];

  const int tid = threadIdx.x;
  const int bl   = tid >> 5;
  const int p    = (tid >> 2) & 7;
  const int s    = (tid >> 1) & 1;
  const int cbit = tid & 1;
  const bool c0  = (cbit == 0);
  const int tq   = tid & 3;

  // stage 0: tail weights -> smem
  if (tid < 8) embph_s[tid] = pr.emb_phase[tid];
  if (tid < 4) { wveh_s[tid] = pr.w_veh[tid]; bveh_s[tid] = pr.b_veh[tid]; }
  for (int i = tid; i < 288; i += NT) wlane_s[i] = pr.w_lane[i];
  if (tid < 16) blane_s[tid] = pr.b_lane[tid];
  for (int i = tid; i < 640; i += NT) wf_s[i] = pr.wf[i];
  if (tid < 20) bf_s[tid] = pr.bf[tid];
  for (int i = tid; i < 400; i += NT) wz_s[i] = pr.wz[i];
  if (tid < 20) bz_s[tid] = pr.bz[tid];
  if (tid < 20) wo_s[tid] = pr.wo[tid];
  if (tid == 0) bo_s = pr.bo[0];
  for (int i = tid; i < 80; i += NT) wc_s[i] = pr.wc[i];
  if (tid < 20) bc_s[tid] = pr.bc[tid];
  if (tid < 8) embc_s[tid] = pr.emb_const[tid];
  if (tid < 56) rel_s[tid] = pr.relation[tid];
  if (tid < PP) pfl_s[tid] = pr.pfl[tid];

  const int b = blockIdx.x * BPB + bl;
  const bool active = (b < pr.B);
  const int bcl = active ? b : (pr.B - 1);

  // ---- weight gather: kk 0..6 register-resident (112 regs) ----
  const float* gwih = pr.gwih;
  const float* gwhh = pr.gwhh;
  auto wat = [&](int kk, int pos) -> float {
    if (pos >= 15) return 0.f;
    int grow;
    if (pos < 10) { int j = pos >> 1, g = pos & 1; grow = g * 10 + 5 * s + j; }
    else          { grow = 20 + 5 * s + (pos - 10); }
    if (c0) {
      if (kk < 4) return gwih[grow * 4 + kk];
      return gwhh[grow * 10 + 5 * s + (kk - 4)];
    } else {
      int hcol = (kk < 2) ? (5 * s + 3 + kk) : (5 * (1 - s) + (kk - 2));
      return gwhh[grow * 10 + hcol];
    }
  };
  ull w[7][8];
#pragma unroll
  for (int kk = 0; kk < 7; kk++)
#pragma unroll
    for (int i = 0; i < 8; i++)
      w[kk][i] = pk2b(wat(kk, 2 * i), wat(kk, 2 * i + 1));

  auto bat = [&](int pos) -> float {
    if (!c0) return 0.f;
    if (pos < 10) { int j = pos >> 1, g = pos & 1; int grow = g * 10 + 5 * s + j;
                    return pr.gbih[grow] + pr.gbhh[grow]; }
    if (pos >= 10 && pos < 15) return pr.gbih[20 + 5 * s + (pos - 10)];  // P (bih_n)
    if (pos >= 16 && pos < 21) return pr.gbhh[20 + 5 * s + (pos - 16)];  // Q (bhh_n)
    return 0.f;
  };
  // biases -> smem table (duplicate writers across warps write identical data)
  if (p == 0) {
    float* dst = &bq_s[tq * 24];
    for (int i = 0; i < 11; i++) {
      dst[2 * i]     = bat(2 * i);
      dst[2 * i + 1] = bat(2 * i + 1);
    }
    dst[22] = 0.f; dst[23] = 0.f;   // pad (last LDS.128 overreads)
  }
  __syncthreads();

  const ulonglong2* bq2 = reinterpret_cast<const ulonglong2*>(&bq_s[tq * 24]);

  // owned h (c0: h0,h1,h2 ; c1: h3,h4,[garbage]); union state u:
  //   c0: u0..u3 = x(t), u4 unused ; c1: u0..u4 = other/own-half h cache.
  float hO[3] = {0.f, 0.f, 0.f};
  float u0 = 0.f, u1 = 0.f, u2 = 0.f, u3 = 0.f, u4 = 0.f;

  const float4* xp = &g_xbuf[(size_t)bcl * TT * PP + p];
  if (c0) {
    float4 x0v = xp[0];
    u0 = x0v.x; u1 = x0v.y; u2 = x0v.z; u3 = x0v.w;
  }

  for (int t = 0; t < TT; t++) {
    float4 xn = make_float4(0.f, 0.f, 0.f, 0.f);
    if (t + 1 < TT && c0) xn = xp[(t + 1) * PP];

    float vals[7];
    vals[0] = c0 ? u0 : hO[0];
    vals[1] = c0 ? u1 : hO[1];
    vals[2] = c0 ? u2 : u0;
    vals[3] = c0 ? u3 : u1;
    vals[4] = c0 ? hO[0] : u2;
    vals[5] = c0 ? hO[1] : u3;
    vals[6] = c0 ? hO[2] : u4;

    // A init from smem bias pairs (loop-invariant broadcast LDS.128)
    ull A[11];
    {
      ulonglong2 b0 = bq2[0], b1 = bq2[1], b2 = bq2[2];
      ulonglong2 b3 = bq2[3], b4 = bq2[4], b5 = bq2[5];
      A[0] = b0.x; A[1] = b0.y; A[2] = b1.x; A[3] = b1.y;
      A[4] = b2.x; A[5] = b2.y; A[6] = b3.x; A[7] = b3.y;
      A[8] = b4.x; A[9] = b4.y; A[10] = b5.x;
    }
#pragma unroll
    for (int kk = 0; kk < 7; kk++) {
      ull s2 = pk2(vals[kk]);
#pragma unroll
      for (int i = 0; i < 5; i++) A[i] = f2fma(s2, w[kk][i], A[i]);
      const int nb = (kk < 4) ? 5 : 8;   // P bucket vs Q bucket
#pragma unroll
      for (int i = 0; i < 3; i++) A[nb + i] = f2fma(s2, w[kk][5 + i], A[nb + i]);
    }

    // c1 pre-sums its full h-side n partial (c0's S unused)
    ull S0 = add2(A[5], A[8]);
    ull S1 = add2(A[6], A[9]);
    ull S2 = add2(A[7], A[10]);

    // asymmetric exchange: 6 ull shfls
    ull r1 = __shfl_xor_sync(0xffffffffu, c0 ? A[3]  : A[0], 1);
    ull r2 = __shfl_xor_sync(0xffffffffu, c0 ? A[4]  : A[1], 1);
    ull r3 = __shfl_xor_sync(0xffffffffu, c0 ? A[6]  : A[2], 1);
    ull r4 = __shfl_xor_sync(0xffffffffu, c0 ? A[7]  : S0,   1);
    ull r5 = __shfl_xor_sync(0xffffffffu, c0 ? A[9]  : S1,   1);
    ull r6 = __shfl_xor_sync(0xffffffffu, c0 ? A[10] : S2,   1);

    // combined RZ for owned slots
    ull rz0 = add2(c0 ? A[0] : A[3], r1);     // c0: j0 ; c1: j3
    ull rz1 = add2(c0 ? A[1] : A[4], r2);     // c0: j1 ; c1: j4
    ull rz2 = add2(A[2], r3);                 // c0: j2 ; c1: garbage
    // c0 hn pairs
    ull hnp0 = add2(r4, A[8]);                // c0: {hn0,hn1}
    ull hnp1 = add2(r5, A[9]);                // c0: {hn2,hn3}

    float gA = c0 ? loF(A[5]) : hiF(r3);
    float hA = c0 ? loF(hnp0) : (hiF(S1) + hiF(r5));
    float gB = c0 ? hiF(A[5]) : loF(r4);
    float hB = c0 ? hiF(hnp0) : (loF(S2) + loF(r6));
    float gC = loF(A[6]);
    float hC = loF(hnp1);

    {
      float rl, zl;
      upk(rz0, rl, zl);
      float rr0 = sigf(rl), zz0 = sigf(zl);
      float nn0 = tanh_ap(fmaf(rr0, hA, gA));
      upk(rz1, rl, zl);
      float rr1 = sigf(rl), zz1 = sigf(zl);
      float nn1 = tanh_ap(fmaf(rr1, hB, gB));
      upk(rz2, rl, zl);
      float rr2 = sigf(rl), zz2 = sigf(zl);
      float nn2 = tanh_ap(fmaf(rr2, hC, gC));
      hO[0] = fmaf(zz0, hO[0] - nn0, nn0);
      hO[1] = fmaf(zz1, hO[1] - nn1, nn1);
      hO[2] = fmaf(zz2, hO[2] - nn2, nn2);   // c1: garbage, never consumed
    }

    // redistribute for next step (only c1 keeps); c0 refreshes x from prefetch
    float w3a = __shfl_xor_sync(0xffffffffu, hO[0], 3);
    float w3b = __shfl_xor_sync(0xffffffffu, hO[1], 3);
    float w3c = __shfl_xor_sync(0xffffffffu, hO[2], 3);
    float w2a = __shfl_xor_sync(0xffffffffu, hO[0], 2);
    float w2b = __shfl_xor_sync(0xffffffffu, hO[1], 2);
    u0 = c0 ? xn.x : w3a;
    u1 = c0 ? xn.y : w3b;
    u2 = c0 ? xn.z : w3c;
    u3 = c0 ? xn.w : w2a;
    u4 = c0 ? 0.f  : w2b;
  }

  // ---- reassemble full h for tail ----
  float ha[10];
  {
    float t1 = __shfl_xor_sync(0xffffffffu, hO[0], 1);  // c0<-h3 ; c1<-h0
    float t2 = __shfl_xor_sync(0xffffffffu, hO[1], 1);  // c0<-h4 ; c1<-h1
    float t3 = __shfl_xor_sync(0xffffffffu, hO[2], 1);  //          c1<-h2
    float hf0 = c0 ? hO[0] : t1;
    float hf1 = c0 ? hO[1] : t2;
    float hf2 = c0 ? hO[2] : t3;
    float hf3 = c0 ? t1 : hO[0];
    float hf4 = c0 ? t2 : hO[1];
    float hg0 = __shfl_xor_sync(0xffffffffu, hf0, 2);
    float hg1 = __shfl_xor_sync(0xffffffffu, hf1, 2);
    float hg2 = __shfl_xor_sync(0xffffffffu, hf2, 2);
    float hg3 = __shfl_xor_sync(0xffffffffu, hf3, 2);
    float hg4 = __shfl_xor_sync(0xffffffffu, hf4, 2);
    float hf[5] = {hf0, hf1, hf2, hf3, hf4};
    float hg[5] = {hg0, hg1, hg2, hg3, hg4};
#pragma unroll
    for (int j = 0; j < 5; j++) {
      ha[j]     = (s == 0) ? hf[j] : hg[j];
      ha[5 + j] = (s == 0) ? hg[j] : hf[j];
    }
  }

  // ---- tail: lane projection -> pressure -> pair network ----
  {
    float lf[18];
    float veh = pr.feat[(size_t)bcl * 16 + 8 + p];
    int pidx = (int)pr.feat[(size_t)bcl * 16 + p];
#pragma unroll
    for (int j = 0; j < 4; j++) lf[j] = sigf(fmaf(veh, wveh_s[j], bveh_s[j]));
#pragma unroll
    for (int j = 0; j < 4; j++) lf[4 + j] = sigf(embph_s[pidx * 4 + j]);
#pragma unroll
    for (int i = 0; i < 10; i++) lf[8 + i] = ha[i];

    const int lrow = bl * 8 + p;
#pragma unroll
    for (int mm = 0; mm < 4; mm++) {
      int m = 4 * tq + mm;
      float acc = blane_s[m];
#pragma unroll
      for (int k = 0; k < 18; k++) acc = fmaf(lf[k], wlane_s[k * 16 + m], acc);
      press_s[lrow * 17 + m] = 2.0f * fmaxf(acc, 0.f);
    }
    __syncwarp();
    float pf[16];
#pragma unroll
    for (int k = 0; k < 16; k++) pf[k] = press_s[lrow * 17 + k];
#pragma unroll
    for (int mm = 0; mm < 5; mm++) {
      int m = 5 * tq + mm;
      float acc = 0.f;
#pragma unroll
      for (int k = 0; k < 16; k++) acc = fmaf(pf[k], wf_s[(16 + k) * 20 + m], acc);
      v_s[lrow * 21 + m] = acc;
    }
    __syncwarp();
  }
  {
    const int iph = p;
    const int li = pfl_s[iph];
    const float* pi = &press_s[(bl * 8 + li) * 17];

    float u[20];
#pragma unroll
    for (int m = 0; m < 20; m++) u[m] = bf_s[m];
#pragma unroll
    for (int k = 0; k < 16; k++) {
      float sv = pi[k];
#pragma unroll
      for (int m = 0; m < 20; m++) u[m] = fmaf(sv, wf_s[k * 20 + m], u[m]);
    }

    float acc = 0.f;
    const int jpS = tq * 2;
    const int jpN = (tq == 3) ? 1 : 2;
    for (int q = 0; q < jpN; q++) {
      int jp = jpS + q;
      int j = jp + (jp >= iph ? 1 : 0);
      int lj = pfl_s[j];
      const float* vj = &v_s[(bl * 8 + lj) * 21];
      int rel = rel_s[iph * 7 + jp];
      const float* e = &embc_s[rel * 4];
      float ttv[20];
#pragma unroll
      for (int m = 0; m < 20; m++) {
        float y = bc_s[m];
#pragma unroll
        for (int c = 0; c < 4; c++) y = fmaf(e[c], wc_s[c * 20 + m], y);
        y = fmaxf(y, 0.f);
        ttv[m] = fmaxf(u[m] + vj[m], 0.f) * y;
      }
      float z2[20];
#pragma unroll
      for (int m = 0; m < 20; m++) z2[m] = bz_s[m];
#pragma unroll
      for (int m = 0; m < 20; m++) {
        float sv = ttv[m];
#pragma unroll
        for (int m2 = 0; m2 < 20; m2++) z2[m2] = fmaf(sv, wz_s[m * 20 + m2], z2[m2]);
      }
      float zs = bo_s;
#pragma unroll
      for (int m2 = 0; m2 < 20; m2++) zs = fmaf(fmaxf(z2[m2], 0.f), wo_s[m2], zs);
      acc += zs;
    }
    acc += __shfl_xor_sync(0xffffffffu, acc, 1);
    acc += __shfl_xor_sync(0xffffffffu, acc, 2);
    if (tq == 0 && active) pr.out[(size_t)b * PP + iph] = acc;
  }
}

extern "C" void kernel_launch(void* const* d_in, const int* in_sizes, int n_in,
                              void* d_out, int out_size) {
  Params pr;
  pr.feat      = (const float*)d_in[0];
  pr.hist      = (const float*)d_in[1];
  pr.relation  = (const int*)  d_in[2];
  pr.pfl       = (const int*)  d_in[3];
  pr.emb_phase = (const float*)d_in[4];
  pr.w_veh     = (const float*)d_in[5];
  pr.b_veh     = (const float*)d_in[6];
  pr.w_hist    = (const float*)d_in[7];
  pr.b_hist    = (const float*)d_in[8];
  pr.gwih      = (const float*)d_in[9];
  pr.gwhh      = (const float*)d_in[10];
  pr.gbih      = (const float*)d_in[11];
  pr.gbhh      = (const float*)d_in[12];
  pr.w_lane    = (const float*)d_in[13];
  pr.b_lane    = (const float*)d_in[14];
  pr.emb_const = (const float*)d_in[15];
  pr.wf        = (const float*)d_in[16];
  pr.bf        = (const float*)d_in[17];
  pr.wc        = (const float*)d_in[18];
  pr.bc        = (const float*)d_in[19];
  pr.wz        = (const float*)d_in[20];
  pr.bz        = (const float*)d_in[21];
  pr.wo        = (const float*)d_in[22];
  pr.bo        = (const float*)d_in[23];
  pr.out       = (float*)d_out;
  pr.B         = in_sizes[0] / (2 * PP);

  long bt = (long)pr.B * TT;
  precomp_x<<<(int)((bt + 255) / 256), 256>>>(pr.hist, pr.w_hist, pr.b_hist, pr.B);
  int grid = (pr.B + BPB - 1) / BPB;
  gru_kernel<<<grid, NT>>>(pr);
}

// round 14
// speedup vs baseline: 1.6423x; 1.5911x over previous
#include <cuda_runtime.h>
#include <cuda_fp16.h>

#define PP 8
#define TT 128
#define BPB 2
#define NT 64
#define MAXB 8192

typedef unsigned long long ull;

struct Params {
  const float* feat; const float* hist; const int* relation; const int* pfl;
  const float* emb_phase; const float* w_veh; const float* b_veh;
  const float* w_hist; const float* b_hist;
  const float* gwih; const float* gwhh; const float* gbih; const float* gbhh;
  const float* w_lane; const float* b_lane; const float* emb_const;
  const float* wf; const float* bf; const float* wc; const float* bc;
  const float* wz; const float* bz; const float* wo; const float* bo;
  float* out; int B;
};

// scratch (static device memory — no allocations): x in fp16 (4 halves = uint2)
__device__ __align__(16) uint2 g_xbuf[(size_t)MAXB * TT * PP];

__device__ __forceinline__ ull pk2(float v) {
  ull d; asm("mov.b64 %0, {%1, %1};" : "=l"(d) : "f"(v)); return d;
}
__device__ __forceinline__ ull pk2b(float lo, float hi) {
  ull d; asm("mov.b64 %0, {%1, %2};" : "=l"(d) : "f"(lo), "f"(hi)); return d;
}
__device__ __forceinline__ ull f2fma(ull a, ull b, ull c) {
  ull d; asm("fma.rn.f32x2 %0, %1, %2, %3;" : "=l"(d) : "l"(a), "l"(b), "l"(c)); return d;
}
__device__ __forceinline__ ull add2(ull a, ull b) {
  ull d; asm("add.rn.f32x2 %0, %1, %2;" : "=l"(d) : "l"(a), "l"(b)); return d;
}
__device__ __forceinline__ void upk(ull v, float& lo, float& hi) {
  asm("mov.b64 {%0, %1}, %2;" : "=f"(lo), "=f"(hi) : "l"(v));
}
__device__ __forceinline__ float loF(ull v) { float a, b; upk(v, a, b); return a; }
__device__ __forceinline__ float hiF(ull v) { float a, b; upk(v, a, b); return b; }
__device__ __forceinline__ float tanh_ap(float x) {
  float y; asm("tanh.approx.f32 %0, %1;" : "=f"(y) : "f"(x)); return y;
}
__device__ __forceinline__ float sigf(float v) {
  return fmaf(tanh_ap(0.5f * v), 0.5f, 0.5f);
}

// ---------------- precompute x = sigmoid(hist @ w_hist + b_hist) -> fp16 ----------------
__global__ __launch_bounds__(256) void precomp_x(const float* __restrict__ hist,
                                                 const float* __restrict__ w_hist,
                                                 const float* __restrict__ b_hist, int B) {
  long idx = (long)blockIdx.x * blockDim.x + threadIdx.x;   // over B*T
  if (idx >= (long)B * TT) return;
  const float4* row4 = reinterpret_cast<const float4*>(hist + idx * 24);
  float q[24];
  float4 rr;
#pragma unroll
  for (int i = 0; i < 6; i++) {
    rr = row4[i];
    q[4 * i] = rr.x; q[4 * i + 1] = rr.y; q[4 * i + 2] = rr.z; q[4 * i + 3] = rr.w;
  }
  float w[12], bb[4];
#pragma unroll
  for (int i = 0; i < 12; i++) w[i] = w_hist[i];
#pragma unroll
  for (int j = 0; j < 4; j++) bb[j] = b_hist[j];
  uint2* dst = &g_xbuf[idx * PP];
#pragma unroll
  for (int p = 0; p < PP; p++) {
    float q0 = q[p], q1 = q[8 + p], q2 = q[16 + p];
    float x0 = sigf(fmaf(q0, w[0], fmaf(q1, w[4], fmaf(q2, w[8],  bb[0]))));
    float x1 = sigf(fmaf(q0, w[1], fmaf(q1, w[5], fmaf(q2, w[9],  bb[1]))));
    float x2 = sigf(fmaf(q0, w[2], fmaf(q1, w[6], fmaf(q2, w[10], bb[2]))));
    float x3 = sigf(fmaf(q0, w[3], fmaf(q1, w[7], fmaf(q2, w[11], bb[3]))));
    __half2 h01 = __floats2half2_rn(x0, x1);
    __half2 h23 = __floats2half2_rn(x2, x3);
    uint2 o;
    o.x = *reinterpret_cast<unsigned int*>(&h01);
    o.y = *reinterpret_cast<unsigned int*>(&h23);
    dst[p] = o;
  }
}

// ---------------- main GRU + tail kernel ----------------
// Round-7 structure (measured best): 4 threads per (batch,lane), s = hidden
// half, c = reduction split, ownership-split combine, weights+biases fully
// register-resident (168 regs, 6 CTAs/SM). Delta vs R7: x buffer is fp16
// (uint2 load, H2F unpack on c0 only), x loads predicated on c0.
__global__ __launch_bounds__(NT, 6) void gru_kernel(Params pr) {
  __shared__ float embph_s[8], wveh_s[4], bveh_s[4];
  __shared__ float wlane_s[18 * 16], blane_s[16];
  __shared__ float wf_s[32 * 20], bf_s[20];
  __shared__ float wz_s[20 * 20], bz_s[20];
  __shared__ float wo_s[20];
  __shared__ float bo_s;
  __shared__ float wc_s[4 * 20], bc_s[20], embc_s[8];
  __shared__ int rel_s[56], pfl_s[PP];
  __shared__ float press_s[BPB * PP * 17];
  __shared__ float v_s[BPB * PP * 21];

  const int tid = threadIdx.x;
  const int bl   = tid >> 5;
  const int p    = (tid >> 2) & 7;
  const int s    = (tid >> 1) & 1;
  const int cbit = tid & 1;
  const bool c0  = (cbit == 0);
  const int tq   = tid & 3;

  // stage 0: tail weights -> smem
  if (tid < 8) embph_s[tid] = pr.emb_phase[tid];
  if (tid < 4) { wveh_s[tid] = pr.w_veh[tid]; bveh_s[tid] = pr.b_veh[tid]; }
  for (int i = tid; i < 288; i += NT) wlane_s[i] = pr.w_lane[i];
  if (tid < 16) blane_s[tid] = pr.b_lane[tid];
  for (int i = tid; i < 640; i += NT) wf_s[i] = pr.wf[i];
  if (tid < 20) bf_s[tid] = pr.bf[tid];
  for (int i = tid; i < 400; i += NT) wz_s[i] = pr.wz[i];
  if (tid < 20) bz_s[tid] = pr.bz[tid];
  if (tid < 20) wo_s[tid] = pr.wo[tid];
  if (tid == 0) bo_s = pr.bo[0];
  for (int i = tid; i < 80; i += NT) wc_s[i] = pr.wc[i];
  if (tid < 20) bc_s[tid] = pr.bc[tid];
  if (tid < 8) embc_s[tid] = pr.emb_const[tid];
  if (tid < 56) rel_s[tid] = pr.relation[tid];
  if (tid < PP) pfl_s[tid] = pr.pfl[tid];

  const long b = (long)blockIdx.x * BPB + bl;
  const bool active = (b < (long)pr.B);
  const long bcl = active ? b : (long)(pr.B - 1);

  // ---- in-kernel weight gather: 56 loop-resident ull regs per thread ----
  const float* gwih = pr.gwih;
  const float* gwhh = pr.gwhh;
  auto wat = [&](int kk, int pos) -> float {
    if (pos >= 15) return 0.f;
    int grow;
    if (pos < 10) { int j = pos >> 1, g = pos & 1; grow = g * 10 + 5 * s + j; }
    else          { grow = 20 + 5 * s + (pos - 10); }
    if (c0) {
      if (kk < 4) return gwih[grow * 4 + kk];
      return gwhh[grow * 10 + 5 * s + (kk - 4)];
    } else {
      int hcol = (kk < 2) ? (5 * s + 3 + kk) : (5 * (1 - s) + (kk - 2));
      return gwhh[grow * 10 + hcol];
    }
  };
  ull w[7][8];
#pragma unroll
  for (int kk = 0; kk < 7; kk++)
#pragma unroll
    for (int i = 0; i < 8; i++)
      w[kk][i] = pk2b(wat(kk, 2 * i), wat(kk, 2 * i + 1));

  auto bat = [&](int pos) -> float {
    if (!c0) return 0.f;
    if (pos < 10) { int j = pos >> 1, g = pos & 1; int grow = g * 10 + 5 * s + j;
                    return pr.gbih[grow] + pr.gbhh[grow]; }
    if (pos >= 10 && pos < 15) return pr.gbih[20 + 5 * s + (pos - 10)];  // P (bih_n)
    if (pos >= 16 && pos < 21) return pr.gbhh[20 + 5 * s + (pos - 16)];  // Q (bhh_n)
    return 0.f;
  };
  ull bias[11];
#pragma unroll
  for (int i = 0; i < 11; i++) bias[i] = pk2b(bat(2 * i), bat(2 * i + 1));

  __syncthreads();

  // owned h (c0: h0,h1,h2 ; c1: h3,h4,[garbage]) and c1's other-half cache
  float hO[3] = {0.f, 0.f, 0.f};
  float hx0 = 0.f, hx1 = 0.f, hx2 = 0.f, hx3 = 0.f, hx4 = 0.f;

  const uint2* xp = &g_xbuf[bcl * TT * PP + p];
  uint2 xq = make_uint2(0u, 0u);
  if (c0) xq = xp[0];                 // c1 never consumes x

  for (int t = 0; t < TT; t++) {
    uint2 xn = make_uint2(0u, 0u);
    if (t + 1 < TT && c0) xn = xp[(t + 1) * PP];

    // unpack fp16 x (meaningful on c0 lanes only)
    float2 xlo = __half22float2(*reinterpret_cast<__half2*>(&xq.x));
    float2 xhi = __half22float2(*reinterpret_cast<__half2*>(&xq.y));

    float vals[7];
    vals[0] = c0 ? xlo.x : hO[0];
    vals[1] = c0 ? xlo.y : hO[1];
    vals[2] = c0 ? xhi.x : hx0;
    vals[3] = c0 ? xhi.y : hx1;
    vals[4] = c0 ? hO[0] : hx2;
    vals[5] = c0 ? hO[1] : hx3;
    vals[6] = c0 ? hO[2] : hx4;

    ull A[11];
    {
      ull s2 = pk2(vals[0]);
#pragma unroll
      for (int i = 0; i < 5; i++) A[i] = f2fma(s2, w[0][i], bias[i]);
#pragma unroll
      for (int i = 0; i < 3; i++) A[5 + i] = f2fma(s2, w[0][5 + i], bias[5 + i]);
      A[8] = bias[8]; A[9] = bias[9]; A[10] = bias[10];
    }
#pragma unroll
    for (int kk = 1; kk < 7; kk++) {
      ull s2 = pk2(vals[kk]);
#pragma unroll
      for (int i = 0; i < 5; i++) A[i] = f2fma(s2, w[kk][i], A[i]);
      const int nb = (kk < 4) ? 5 : 8;
#pragma unroll
      for (int i = 0; i < 3; i++) A[nb + i] = f2fma(s2, w[kk][5 + i], A[nb + i]);
    }

    // c1 pre-sums its full h-side n partial (c0's S unused)
    ull S0 = add2(A[5], A[8]);
    ull S1 = add2(A[6], A[9]);
    ull S2 = add2(A[7], A[10]);

    // asymmetric exchange: 6 ull shfls
    ull r1 = __shfl_xor_sync(0xffffffffu, c0 ? A[3]  : A[0], 1);
    ull r2 = __shfl_xor_sync(0xffffffffu, c0 ? A[4]  : A[1], 1);
    ull r3 = __shfl_xor_sync(0xffffffffu, c0 ? A[6]  : A[2], 1);
    ull r4 = __shfl_xor_sync(0xffffffffu, c0 ? A[7]  : S0,   1);
    ull r5 = __shfl_xor_sync(0xffffffffu, c0 ? A[9]  : S1,   1);
    ull r6 = __shfl_xor_sync(0xffffffffu, c0 ? A[10] : S2,   1);

    // combined RZ for owned slots
    ull rz0 = add2(c0 ? A[0] : A[3], r1);     // c0: j0 ; c1: j3
    ull rz1 = add2(c0 ? A[1] : A[4], r2);     // c0: j1 ; c1: j4
    ull rz2 = add2(A[2], r3);                 // c0: j2 ; c1: garbage
    // c0 hn pairs
    ull hnp0 = add2(r4, A[8]);                // c0: {hn0,hn1}
    ull hnp1 = add2(r5, A[9]);                // c0: {hn2,hn3}

    float gA = c0 ? loF(A[5]) : hiF(r3);
    float hA = c0 ? loF(hnp0) : (hiF(S1) + hiF(r5));
    float gB = c0 ? hiF(A[5]) : loF(r4);
    float hB = c0 ? hiF(hnp0) : (loF(S2) + loF(r6));
    float gC = loF(A[6]);
    float hC = loF(hnp1);

    {
      float rl, zl;
      upk(rz0, rl, zl);
      float rr0 = sigf(rl), zz0 = sigf(zl);
      float nn0 = tanh_ap(fmaf(rr0, hA, gA));
      upk(rz1, rl, zl);
      float rr1 = sigf(rl), zz1 = sigf(zl);
      float nn1 = tanh_ap(fmaf(rr1, hB, gB));
      upk(rz2, rl, zl);
      float rr2 = sigf(rl), zz2 = sigf(zl);
      float nn2 = tanh_ap(fmaf(rr2, hC, gC));
      hO[0] = fmaf(zz0, hO[0] - nn0, nn0);
      hO[1] = fmaf(zz1, hO[1] - nn1, nn1);
      hO[2] = fmaf(zz2, hO[2] - nn2, nn2);   // c1: garbage, never consumed
    }

    // redistribute for next step: only c1 consumes these
    float w3a = __shfl_xor_sync(0xffffffffu, hO[0], 3);
    float w3b = __shfl_xor_sync(0xffffffffu, hO[1], 3);
    float w3c = __shfl_xor_sync(0xffffffffu, hO[2], 3);
    float w2a = __shfl_xor_sync(0xffffffffu, hO[0], 2);
    float w2b = __shfl_xor_sync(0xffffffffu, hO[1], 2);
    hx0 = w3a; hx1 = w3b; hx2 = w3c; hx3 = w2a; hx4 = w2b;

    xq = xn;
  }

  // ---- reassemble full h for tail ----
  float ha[10];
  {
    float t1 = __shfl_xor_sync(0xffffffffu, hO[0], 1);  // c0<-h3 ; c1<-h0
    float t2 = __shfl_xor_sync(0xffffffffu, hO[1], 1);  // c0<-h4 ; c1<-h1
    float t3 = __shfl_xor_sync(0xffffffffu, hO[2], 1);  //          c1<-h2
    float hf0 = c0 ? hO[0] : t1;
    float hf1 = c0 ? hO[1] : t2;
    float hf2 = c0 ? hO[2] : t3;
    float hf3 = c0 ? t1 : hO[0];
    float hf4 = c0 ? t2 : hO[1];
    float hg0 = __shfl_xor_sync(0xffffffffu, hf0, 2);
    float hg1 = __shfl_xor_sync(0xffffffffu, hf1, 2);
    float hg2 = __shfl_xor_sync(0xffffffffu, hf2, 2);
    float hg3 = __shfl_xor_sync(0xffffffffu, hf3, 2);
    float hg4 = __shfl_xor_sync(0xffffffffu, hf4, 2);
    float hf[5] = {hf0, hf1, hf2, hf3, hf4};
    float hg[5] = {hg0, hg1, hg2, hg3, hg4};
#pragma unroll
    for (int j = 0; j < 5; j++) {
      ha[j]     = (s == 0) ? hf[j] : hg[j];
      ha[5 + j] = (s == 0) ? hg[j] : hf[j];
    }
  }

  // ---- tail: lane projection -> pressure -> pair network ----
  {
    float lf[18];
    float veh = pr.feat[bcl * 16 + 8 + p];
    int pidx = (int)pr.feat[bcl * 16 + p];
#pragma unroll
    for (int j = 0; j < 4; j++) lf[j] = sigf(fmaf(veh, wveh_s[j], bveh_s[j]));
#pragma unroll
    for (int j = 0; j < 4; j++) lf[4 + j] = sigf(embph_s[pidx * 4 + j]);
#pragma unroll
    for (int i = 0; i < 10; i++) lf[8 + i] = ha[i];

    const int lrow = bl * 8 + p;
#pragma unroll
    for (int mm = 0; mm < 4; mm++) {
      int m = 4 * tq + mm;
      float acc = blane_s[m];
#pragma unroll
      for (int k = 0; k < 18; k++) acc = fmaf(lf[k], wlane_s[k * 16 + m], acc);
      press_s[lrow * 17 + m] = 2.0f * fmaxf(acc, 0.f);
    }
    __syncwarp();
    float pf[16];
#pragma unroll
    for (int k = 0; k < 16; k++) pf[k] = press_s[lrow * 17 + k];
#pragma unroll
    for (int mm = 0; mm < 5; mm++) {
      int m = 5 * tq + mm;
      float acc = 0.f;
#pragma unroll
      for (int k = 0; k < 16; k++) acc = fmaf(pf[k], wf_s[(16 + k) * 20 + m], acc);
      v_s[lrow * 21 + m] = acc;
    }
    __syncwarp();
  }
  {
    const int iph = p;
    const int li = pfl_s[iph];
    const float* pi = &press_s[(bl * 8 + li) * 17];

    float u[20];
#pragma unroll
    for (int m = 0; m < 20; m++) u[m] = bf_s[m];
#pragma unroll
    for (int k = 0; k < 16; k++) {
      float sv = pi[k];
#pragma unroll
      for (int m = 0; m < 20; m++) u[m] = fmaf(sv, wf_s[k * 20 + m], u[m]);
    }

    float acc = 0.f;
    const int jpS = tq * 2;
    const int jpN = (tq == 3) ? 1 : 2;
    for (int q = 0; q < jpN; q++) {
      int jp = jpS + q;
      int j = jp + (jp >= iph ? 1 : 0);
      int lj = pfl_s[j];
      const float* vj = &v_s[(bl * 8 + lj) * 21];
      int rel = rel_s[iph * 7 + jp];
      const float* e = &embc_s[rel * 4];
      float ttv[20];
#pragma unroll
      for (int m = 0; m < 20; m++) {
        float y = bc_s[m];
#pragma unroll
        for (int c = 0; c < 4; c++) y = fmaf(e[c], wc_s[c * 20 + m], y);
        y = fmaxf(y, 0.f);
        ttv[m] = fmaxf(u[m] + vj[m], 0.f) * y;
      }
      float z2[20];
#pragma unroll
      for (int m = 0; m < 20; m++) z2[m] = bz_s[m];
#pragma unroll
      for (int m = 0; m < 20; m++) {
        float sv = ttv[m];
#pragma unroll
        for (int m2 = 0; m2 < 20; m2++) z2[m2] = fmaf(sv, wz_s[m * 20 + m2], z2[m2]);
      }
      float zs = bo_s;
#pragma unroll
      for (int m2 = 0; m2 < 20; m2++) zs = fmaf(fmaxf(z2[m2], 0.f), wo_s[m2], zs);
      acc += zs;
    }
    acc += __shfl_xor_sync(0xffffffffu, acc, 1);
    acc += __shfl_xor_sync(0xffffffffu, acc, 2);
    if (tq == 0 && active) pr.out[b * PP + iph] = acc;
  }
}

extern "C" void kernel_launch(void* const* d_in, const int* in_sizes, int n_in,
                              void* d_out, int out_size) {
  Params pr;
  pr.feat      = (const float*)d_in[0];
  pr.hist      = (const float*)d_in[1];
  pr.relation  = (const int*)  d_in[2];
  pr.pfl       = (const int*)  d_in[3];
  pr.emb_phase = (const float*)d_in[4];
  pr.w_veh     = (const float*)d_in[5];
  pr.b_veh     = (const float*)d_in[6];
  pr.w_hist    = (const float*)d_in[7];
  pr.b_hist    = (const float*)d_in[8];
  pr.gwih      = (const float*)d_in[9];
  pr.gwhh      = (const float*)d_in[10];
  pr.gbih      = (const float*)d_in[11];
  pr.gbhh      = (const float*)d_in[12];
  pr.w_lane    = (const float*)d_in[13];
  pr.b_lane    = (const float*)d_in[14];
  pr.emb_const = (const float*)d_in[15];
  pr.wf        = (const float*)d_in[16];
  pr.bf        = (const float*)d_in[17];
  pr.wc        = (const float*)d_in[18];
  pr.bc        = (const float*)d_in[19];
  pr.wz        = (const float*)d_in[20];
  pr.bz        = (const float*)d_in[21];
  pr.wo        = (const float*)d_in[22];
  pr.bo        = (const float*)d_in[23];
  pr.out       = (float*)d_out;
  pr.B         = in_sizes[0] / (2 * PP);

  long bt = (long)pr.B * TT;
  precomp_x<<<(int)((bt + 255) / 256), 256>>>(pr.hist, pr.w_hist, pr.b_hist, pr.B);
  int grid = (pr.B + BPB - 1) / BPB;
  gru_kernel<<<grid, NT>>>(pr);
}

// round 16
// speedup vs baseline: 1.6504x; 1.0049x over previous
#include <cuda_runtime.h>
#include <cuda_fp16.h>

#define PP 8
#define TT 128
#define BPB 2
#define NT 64
#define MAXB 8192

typedef unsigned long long ull;

struct Params {
  const float* feat; const float* hist; const int* relation; const int* pfl;
  const float* emb_phase; const float* w_veh; const float* b_veh;
  const float* w_hist; const float* b_hist;
  const float* gwih; const float* gwhh; const float* gbih; const float* gbhh;
  const float* w_lane; const float* b_lane; const float* emb_const;
  const float* wf; const float* bf; const float* wc; const float* bc;
  const float* wz; const float* bz; const float* wo; const float* bo;
  float* out; int B;
};

// scratch (static device memory — no allocations): x in fp16 (4 halves = uint2)
__device__ __align__(16) uint2 g_xbuf[(size_t)MAXB * TT * PP];

__device__ __forceinline__ ull pk2(float v) {
  ull d; asm("mov.b64 %0, {%1, %1};" : "=l"(d) : "f"(v)); return d;
}
__device__ __forceinline__ ull pk2b(float lo, float hi) {
  ull d; asm("mov.b64 %0, {%1, %2};" : "=l"(d) : "f"(lo), "f"(hi)); return d;
}
__device__ __forceinline__ ull f2fma(ull a, ull b, ull c) {
  ull d; asm("fma.rn.f32x2 %0, %1, %2, %3;" : "=l"(d) : "l"(a), "l"(b), "l"(c)); return d;
}
__device__ __forceinline__ ull add2(ull a, ull b) {
  ull d; asm("add.rn.f32x2 %0, %1, %2;" : "=l"(d) : "l"(a), "l"(b)); return d;
}
__device__ __forceinline__ void upk(ull v, float& lo, float& hi) {
  asm("mov.b64 {%0, %1}, %2;" : "=f"(lo), "=f"(hi) : "l"(v));
}
__device__ __forceinline__ float loF(ull v) { float a, b; upk(v, a, b); return a; }
__device__ __forceinline__ float hiF(ull v) { float a, b; upk(v, a, b); return b; }
__device__ __forceinline__ float tanh_ap(float x) {
  float y; asm("tanh.approx.f32 %0, %1;" : "=f"(y) : "f"(x)); return y;
}
__device__ __forceinline__ float sigf(float v) {
  return fmaf(tanh_ap(0.5f * v), 0.5f, 0.5f);
}

// ---------------- precompute x = sigmoid(hist @ w_hist + b_hist) -> fp16 ----------------
__global__ __launch_bounds__(256) void precomp_x(const float* __restrict__ hist,
                                                 const float* __restrict__ w_hist,
                                                 const float* __restrict__ b_hist, int B) {
  long idx = (long)blockIdx.x * blockDim.x + threadIdx.x;   // over B*T
  if (idx >= (long)B * TT) return;
  const float4* row4 = reinterpret_cast<const float4*>(hist + idx * 24);
  float q[24];
  float4 rr;
#pragma unroll
  for (int i = 0; i < 6; i++) {
    rr = row4[i];
    q[4 * i] = rr.x; q[4 * i + 1] = rr.y; q[4 * i + 2] = rr.z; q[4 * i + 3] = rr.w;
  }
  float w[12], bb[4];
#pragma unroll
  for (int i = 0; i < 12; i++) w[i] = w_hist[i];
#pragma unroll
  for (int j = 0; j < 4; j++) bb[j] = b_hist[j];
  uint2* dst = &g_xbuf[idx * PP];
#pragma unroll
  for (int p = 0; p < PP; p++) {
    float q0 = q[p], q1 = q[8 + p], q2 = q[16 + p];
    float x0 = sigf(fmaf(q0, w[0], fmaf(q1, w[4], fmaf(q2, w[8],  bb[0]))));
    float x1 = sigf(fmaf(q0, w[1], fmaf(q1, w[5], fmaf(q2, w[9],  bb[1]))));
    float x2 = sigf(fmaf(q0, w[2], fmaf(q1, w[6], fmaf(q2, w[10], bb[2]))));
    float x3 = sigf(fmaf(q0, w[3], fmaf(q1, w[7], fmaf(q2, w[11], bb[3]))));
    __half2 h01 = __floats2half2_rn(x0, x1);
    __half2 h23 = __floats2half2_rn(x2, x3);
    uint2 o;
    o.x = *reinterpret_cast<unsigned int*>(&h01);
    o.y = *reinterpret_cast<unsigned int*>(&h23);
    dst[p] = o;
  }
}

// ---------------- main GRU + tail kernel ----------------
// 4 threads per (batch,lane): s = hidden half, c = reduction split.
// Shadow-x pipelining: x rounds (2/thread: c0 x0,x1; c1 x2,x3) build next-step
// partials (Ax rz slots + AxP gn bucket) during the current step's activation
// stalls. Main serial block = 5 h rounds (c0: hs0..2,ho0,ho1; c1: hs3,hs4,
// ho2,ho3,ho4). Ownership unchanged: c0 -> h0,h1,h2 ; c1 -> h3,h4.
__global__ __launch_bounds__(NT, 5) void gru_kernel(Params pr) {
  __shared__ float embph_s[8], wveh_s[4], bveh_s[4];
  __shared__ float wlane_s[18 * 16], blane_s[16];
  __shared__ float wf_s[32 * 20], bf_s[20];
  __shared__ float wz_s[20 * 20], bz_s[20];
  __shared__ float wo_s[20];
  __shared__ float bo_s;
  __shared__ float wc_s[4 * 20], bc_s[20], embc_s[8];
  __shared__ int rel_s[56], pfl_s[PP];
  __shared__ float press_s[BPB * PP * 17];
  __shared__ float v_s[BPB * PP * 21];

  const int tid = threadIdx.x;
  const int bl   = tid >> 5;
  const int p    = (tid >> 2) & 7;
  const int s    = (tid >> 1) & 1;
  const int cbit = tid & 1;
  const bool c0  = (cbit == 0);
  const int tq   = tid & 3;

  // stage 0: tail weights -> smem
  if (tid < 8) embph_s[tid] = pr.emb_phase[tid];
  if (tid < 4) { wveh_s[tid] = pr.w_veh[tid]; bveh_s[tid] = pr.b_veh[tid]; }
  for (int i = tid; i < 288; i += NT) wlane_s[i] = pr.w_lane[i];
  if (tid < 16) blane_s[tid] = pr.b_lane[tid];
  for (int i = tid; i < 640; i += NT) wf_s[i] = pr.wf[i];
  if (tid < 20) bf_s[tid] = pr.bf[tid];
  for (int i = tid; i < 400; i += NT) wz_s[i] = pr.wz[i];
  if (tid < 20) bz_s[tid] = pr.bz[tid];
  if (tid < 20) wo_s[tid] = pr.wo[tid];
  if (tid == 0) bo_s = pr.bo[0];
  for (int i = tid; i < 80; i += NT) wc_s[i] = pr.wc[i];
  if (tid < 20) bc_s[tid] = pr.bc[tid];
  if (tid < 8) embc_s[tid] = pr.emb_const[tid];
  if (tid < 56) rel_s[tid] = pr.relation[tid];
  if (tid < PP) pfl_s[tid] = pr.pfl[tid];

  const long b = (long)blockIdx.x * BPB + bl;
  const bool active = (b < (long)pr.B);
  const long bcl = active ? b : (long)(pr.B - 1);

  // ---- weight gather ----
  const float* gwih = pr.gwih;
  const float* gwhh = pr.gwhh;
  // gate row for slot position (interleaved rz; n rows 20..29)
  auto growf = [&](int pos) -> int {
    if (pos < 10) return (pos & 1) * 10 + 5 * s + (pos >> 1);
    return 20 + 5 * s + (pos - 10);
  };
  // main h rows: c0 kk0..2 = hs0..2, kk3..4 = ho0,ho1 ;
  //              c1 kk0..1 = hs3,hs4, kk2..4 = ho2,ho3,ho4
  auto wmv = [&](int kk, int pos) -> float {
    if (pos >= 15) return 0.f;
    int hcol;
    if (c0) hcol = (kk < 3) ? (5 * s + kk) : (5 * (1 - s) + (kk - 3));
    else    hcol = (kk < 2) ? (5 * s + 3 + kk) : (5 * (1 - s) + kk);
    return gwhh[growf(pos) * 10 + hcol];
  };
  // shadow x rows: c0 -> x0,x1 ; c1 -> x2,x3
  auto wsv = [&](int m, int pos) -> float {
    if (pos >= 15) return 0.f;
    int xcol = c0 ? m : (2 + m);
    return gwih[growf(pos) * 4 + xcol];
  };
  ull wm[5][8], ws[2][8];
#pragma unroll
  for (int kk = 0; kk < 5; kk++)
#pragma unroll
    for (int i = 0; i < 8; i++)
      wm[kk][i] = pk2b(wmv(kk, 2 * i), wmv(kk, 2 * i + 1));
#pragma unroll
  for (int m = 0; m < 2; m++)
#pragma unroll
    for (int i = 0; i < 8; i++)
      ws[m][i] = pk2b(wsv(m, 2 * i), wsv(m, 2 * i + 1));

  // biases: counted once (c0 only). RZ sums + P (bih_n) fold into shadow
  // round-0 addends; Q (bhh_n) folds into main round-0 addend.
  auto brz = [&](int pos) -> float {
    if (!c0 || pos >= 10) return 0.f;
    int grow = (pos & 1) * 10 + 5 * s + (pos >> 1);
    return pr.gbih[grow] + pr.gbhh[grow];
  };
  auto bnp = [&](const float* src, int j) -> float {
    if (!c0 || j >= 5) return 0.f;
    return src[20 + 5 * s + j];
  };
  ull biasRZ[5], biasP[3], biasQ[3];
#pragma unroll
  for (int i = 0; i < 5; i++) biasRZ[i] = pk2b(brz(2 * i), brz(2 * i + 1));
#pragma unroll
  for (int i = 0; i < 3; i++) {
    biasP[i] = pk2b(bnp(pr.gbih, 2 * i), bnp(pr.gbih, 2 * i + 1));
    biasQ[i] = pk2b(bnp(pr.gbhh, 2 * i), bnp(pr.gbhh, 2 * i + 1));
  }

  __syncthreads();

  // persistent state
  float hO[3] = {0.f, 0.f, 0.f};
  float e1 = 0.f, e2 = 0.f, e3 = 0.f;
  ull Ax[5], AxP[3];

  const uint2* xp = &g_xbuf[bcl * TT * PP + p];

  // prologue: build Ax/AxP for t=0 from x(0)
  {
    uint2 x0v = xp[0];
    unsigned int xs = c0 ? x0v.x : x0v.y;
    float2 xv = __half22float2(*reinterpret_cast<__half2*>(&xs));
    ull s0 = pk2(xv.x), s1 = pk2(xv.y);
#pragma unroll
    for (int i = 0; i < 5; i++) Ax[i] = f2fma(s0, ws[0][i], biasRZ[i]);
#pragma unroll
    for (int i = 0; i < 3; i++) AxP[i] = f2fma(s0, ws[0][5 + i], biasP[i]);
#pragma unroll
    for (int i = 0; i < 5; i++) Ax[i] = f2fma(s1, ws[1][i], Ax[i]);
#pragma unroll
    for (int i = 0; i < 3; i++) AxP[i] = f2fma(s1, ws[1][5 + i], AxP[i]);
  }

  for (int t = 0; t < TT; t++) {
    uint2 xn = make_uint2(0u, 0u);
    if (t + 1 < TT) xn = xp[(t + 1) * PP];

    float vals[5];
    vals[0] = hO[0];
    vals[1] = hO[1];
    vals[2] = c0 ? hO[2] : e3;
    vals[3] = e1;
    vals[4] = e2;

    // ---- main: 5 serial h rounds; A starts from Ax (rz) / biasQ (Q) ----
    ull A0, A1, A2, A3, A4, Q0, Q1, Q2;
    {
      ull s2 = pk2(vals[0]);
      A0 = f2fma(s2, wm[0][0], Ax[0]);
      A1 = f2fma(s2, wm[0][1], Ax[1]);
      A2 = f2fma(s2, wm[0][2], Ax[2]);
      A3 = f2fma(s2, wm[0][3], Ax[3]);
      A4 = f2fma(s2, wm[0][4], Ax[4]);
      Q0 = f2fma(s2, wm[0][5], biasQ[0]);
      Q1 = f2fma(s2, wm[0][6], biasQ[1]);
      Q2 = f2fma(s2, wm[0][7], biasQ[2]);
    }
#pragma unroll
    for (int kk = 1; kk < 5; kk++) {
      ull s2 = pk2(vals[kk]);
      A0 = f2fma(s2, wm[kk][0], A0);
      A1 = f2fma(s2, wm[kk][1], A1);
      A2 = f2fma(s2, wm[kk][2], A2);
      A3 = f2fma(s2, wm[kk][3], A3);
      A4 = f2fma(s2, wm[kk][4], A4);
      Q0 = f2fma(s2, wm[kk][5], Q0);
      Q1 = f2fma(s2, wm[kk][6], Q1);
      Q2 = f2fma(s2, wm[kk][7], Q2);
    }

    // ---- exchange payload packs ----
    ull ownP34 = pk2b(hiF(AxP[1]), loF(AxP[2]));   // {Pn3, Pn4}
    ull ownQ34 = pk2b(hiF(Q1), loF(Q2));           // {Qn3, Qn4}
    ull p6c1   = pk2b(loF(AxP[1]), loF(Q1));       // c1 sends {Pn2, Qn2}

    ull rcv1 = __shfl_xor_sync(0xffffffffu, c0 ? A3 : A0, 1);
    ull rcv2 = __shfl_xor_sync(0xffffffffu, c0 ? A4 : A1, 1);
    ull rcv3 = __shfl_xor_sync(0xffffffffu, c0 ? ownP34 : A2, 1);
    ull rcv4 = __shfl_xor_sync(0xffffffffu, c0 ? ownQ34 : AxP[0], 1);
    ull rcv5 = __shfl_xor_sync(0xffffffffu, c0 ? 0ull : Q0, 1);
    ull rcv6 = __shfl_xor_sync(0xffffffffu, c0 ? 0ull : p6c1, 1);

    // ---- combine (ownership: c0 j0,j1,j2 ; c1 j3,j4) ----
    ull rz0s = add2(c0 ? A0 : A3, rcv1);
    ull rz1s = add2(c0 ? A1 : A4, rcv2);
    ull rz2s = add2(A2, rcv3);                     // c1: garbage, never consumed
    ull gnAB = add2(c0 ? AxP[0] : ownP34, c0 ? rcv4 : rcv3);
    ull hnAB = add2(c0 ? Q0 : ownQ34,     c0 ? rcv5 : rcv4);
    float gC = loF(AxP[1]) + loF(rcv6);            // c0-valid (c1 adds 0)
    float hC = loF(Q1) + hiF(rcv6);                // c0-valid
    float gA = loF(gnAB), gB = hiF(gnAB);
    float hA = loF(hnAB), hB = hiF(hnAB);

    // ---- shadow: rebuild Ax/AxP for next step from xn (fills stalls) ----
    {
      unsigned int xs = c0 ? xn.x : xn.y;
      float2 xv = __half22float2(*reinterpret_cast<__half2*>(&xs));
      ull s0 = pk2(xv.x), s1 = pk2(xv.y);
#pragma unroll
      for (int i = 0; i < 5; i++) Ax[i] = f2fma(s0, ws[0][i], biasRZ[i]);
#pragma unroll
      for (int i = 0; i < 3; i++) AxP[i] = f2fma(s0, ws[0][5 + i], biasP[i]);
#pragma unroll
      for (int i = 0; i < 5; i++) Ax[i] = f2fma(s1, ws[1][i], Ax[i]);
#pragma unroll
      for (int i = 0; i < 3; i++) AxP[i] = f2fma(s1, ws[1][5 + i], AxP[i]);
    }

    // ---- activations + h update ----
    {
      float rl, zl;
      upk(rz0s, rl, zl);
      float rr0 = sigf(rl), zz0 = sigf(zl);
      float nn0 = tanh_ap(fmaf(rr0, hA, gA));
      upk(rz1s, rl, zl);
      float rr1 = sigf(rl), zz1 = sigf(zl);
      float nn1 = tanh_ap(fmaf(rr1, hB, gB));
      upk(rz2s, rl, zl);
      float rr2 = sigf(rl), zz2 = sigf(zl);
      float nn2 = tanh_ap(fmaf(rr2, hC, gC));
      hO[0] = fmaf(zz0, hO[0] - nn0, nn0);
      hO[1] = fmaf(zz1, hO[1] - nn1, nn1);
      hO[2] = fmaf(zz2, hO[2] - nn2, nn2);   // c1: garbage, never consumed
    }

    // ---- redistribution: 3 shfls ----
    e1 = __shfl_xor_sync(0xffffffffu, hO[0], 2);
    e2 = __shfl_xor_sync(0xffffffffu, hO[1], 2);
    e3 = __shfl_xor_sync(0xffffffffu, hO[2], 3);
  }

  // ---- reassemble full h for tail (ownership same as R14) ----
  float ha[10];
  {
    float t1 = __shfl_xor_sync(0xffffffffu, hO[0], 1);  // c0<-h3 ; c1<-h0
    float t2 = __shfl_xor_sync(0xffffffffu, hO[1], 1);  // c0<-h4 ; c1<-h1
    float t3 = __shfl_xor_sync(0xffffffffu, hO[2], 1);  //          c1<-h2
    float hf0 = c0 ? hO[0] : t1;
    float hf1 = c0 ? hO[1] : t2;
    float hf2 = c0 ? hO[2] : t3;
    float hf3 = c0 ? t1 : hO[0];
    float hf4 = c0 ? t2 : hO[1];
    float hg0 = __shfl_xor_sync(0xffffffffu, hf0, 2);
    float hg1 = __shfl_xor_sync(0xffffffffu, hf1, 2);
    float hg2 = __shfl_xor_sync(0xffffffffu, hf2, 2);
    float hg3 = __shfl_xor_sync(0xffffffffu, hf3, 2);
    float hg4 = __shfl_xor_sync(0xffffffffu, hf4, 2);
    float hf[5] = {hf0, hf1, hf2, hf3, hf4};
    float hg[5] = {hg0, hg1, hg2, hg3, hg4};
#pragma unroll
    for (int j = 0; j < 5; j++) {
      ha[j]     = (s == 0) ? hf[j] : hg[j];
      ha[5 + j] = (s == 0) ? hg[j] : hf[j];
    }
  }

  // ---- tail: lane projection -> pressure -> pair network ----
  {
    float lf[18];
    float veh = pr.feat[bcl * 16 + 8 + p];
    int pidx = (int)pr.feat[bcl * 16 + p];
#pragma unroll
    for (int j = 0; j < 4; j++) lf[j] = sigf(fmaf(veh, wveh_s[j], bveh_s[j]));
#pragma unroll
    for (int j = 0; j < 4; j++) lf[4 + j] = sigf(embph_s[pidx * 4 + j]);
#pragma unroll
    for (int i = 0; i < 10; i++) lf[8 + i] = ha[i];

    const int lrow = bl * 8 + p;
#pragma unroll
    for (int mm = 0; mm < 4; mm++) {
      int m = 4 * tq + mm;
      float acc = blane_s[m];
#pragma unroll
      for (int k = 0; k < 18; k++) acc = fmaf(lf[k], wlane_s[k * 16 + m], acc);
      press_s[lrow * 17 + m] = 2.0f * fmaxf(acc, 0.f);
    }
    __syncwarp();
    float pf[16];
#pragma unroll
    for (int k = 0; k < 16; k++) pf[k] = press_s[lrow * 17 + k];
#pragma unroll
    for (int mm = 0; mm < 5; mm++) {
      int m = 5 * tq + mm;
      float acc = 0.f;
#pragma unroll
      for (int k = 0; k < 16; k++) acc = fmaf(pf[k], wf_s[(16 + k) * 20 + m], acc);
      v_s[lrow * 21 + m] = acc;
    }
    __syncwarp();
  }
  {
    const int iph = p;
    const int li = pfl_s[iph];
    const float* pi = &press_s[(bl * 8 + li) * 17];

    float u[20];
#pragma unroll
    for (int m = 0; m < 20; m++) u[m] = bf_s[m];
#pragma unroll
    for (int k = 0; k < 16; k++) {
      float sv = pi[k];
#pragma unroll
      for (int m = 0; m < 20; m++) u[m] = fmaf(sv, wf_s[k * 20 + m], u[m]);
    }

    float acc = 0.f;
    const int jpS = tq * 2;
    const int jpN = (tq == 3) ? 1 : 2;
    for (int q = 0; q < jpN; q++) {
      int jp = jpS + q;
      int j = jp + (jp >= iph ? 1 : 0);
      int lj = pfl_s[j];
      const float* vj = &v_s[(bl * 8 + lj) * 21];
      int rel = rel_s[iph * 7 + jp];
      const float* e = &embc_s[rel * 4];
      float ttv[20];
#pragma unroll
      for (int m = 0; m < 20; m++) {
        float y = bc_s[m];
#pragma unroll
        for (int c = 0; c < 4; c++) y = fmaf(e[c], wc_s[c * 20 + m], y);
        y = fmaxf(y, 0.f);
        ttv[m] = fmaxf(u[m] + vj[m], 0.f) * y;
      }
      float z2[20];
#pragma unroll
      for (int m = 0; m < 20; m++) z2[m] = bz_s[m];
#pragma unroll
      for (int m = 0; m < 20; m++) {
        float sv = ttv[m];
#pragma unroll
        for (int m2 = 0; m2 < 20; m2++) z2[m2] = fmaf(sv, wz_s[m * 20 + m2], z2[m2]);
      }
      float zs = bo_s;
#pragma unroll
      for (int m2 = 0; m2 < 20; m2++) zs = fmaf(fmaxf(z2[m2], 0.f), wo_s[m2], zs);
      acc += zs;
    }
    acc += __shfl_xor_sync(0xffffffffu, acc, 1);
    acc += __shfl_xor_sync(0xffffffffu, acc, 2);
    if (tq == 0 && active) pr.out[b * PP + iph] = acc;
  }
}

extern "C" void kernel_launch(void* const* d_in, const int* in_sizes, int n_in,
                              void* d_out, int out_size) {
  Params pr;
  pr.feat      = (const float*)d_in[0];
  pr.hist      = (const float*)d_in[1];
  pr.relation  = (const int*)  d_in[2];
  pr.pfl       = (const int*)  d_in[3];
  pr.emb_phase = (const float*)d_in[4];
  pr.w_veh     = (const float*)d_in[5];
  pr.b_veh     = (const float*)d_in[6];
  pr.w_hist    = (const float*)d_in[7];
  pr.b_hist    = (const float*)d_in[8];
  pr.gwih      = (const float*)d_in[9];
  pr.gwhh      = (const float*)d_in[10];
  pr.gbih      = (const float*)d_in[11];
  pr.gbhh      = (const float*)d_in[12];
  pr.w_lane    = (const float*)d_in[13];
  pr.b_lane    = (const float*)d_in[14];
  pr.emb_const = (const float*)d_in[15];
  pr.wf        = (const float*)d_in[16];
  pr.bf        = (const float*)d_in[17];
  pr.wc        = (const float*)d_in[18];
  pr.bc        = (const float*)d_in[19];
  pr.wz        = (const float*)d_in[20];
  pr.bz        = (const float*)d_in[21];
  pr.wo        = (const float*)d_in[22];
  pr.bo        = (const float*)d_in[23];
  pr.out       = (float*)d_out;
  pr.B         = in_sizes[0] / (2 * PP);

  long bt = (long)pr.B * TT;
  precomp_x<<<(int)((bt + 255) / 256), 256>>>(pr.hist, pr.w_hist, pr.b_hist, pr.B);
  int grid = (pr.B + BPB - 1) / BPB;
  gru_kernel<<<grid, NT>>>(pr);
}